// round 13
// baseline (speedup 1.0000x reference)
#include <cuda_runtime.h>
#include <mma.h>
#include <math.h>

using namespace nvcuda;

#define N_NODES 50000
#define E_EDGES 800000
#define P_PATHS 3
#define IN_DIM  128
#define H_HEADS 8
#define D_DIM   32
#define HD      256   // H*D
#define PHD     768   // P*H*D
#define EMB     128
#define PN      (P_PATHS * N_NODES)        // 150000
#define PE      (P_PATHS * E_EDGES)        // 2400000
#define A_CAP   64

// ---- scratch (static device memory) ----
__device__ float g_feat[(size_t)P_PATHS * N_NODES * HD];   // 153.6 MB
__device__ float g_el  [PN * H_HEADS];
__device__ float g_er  [PN * H_HEADS];
__device__ float g_z   [(size_t)N_NODES * PHD];            // 153.6 MB (post-ELU)
__device__ float g_wa  [P_PATHS * IN_DIM * 16];            // [p][k][16]: 0-7 el, 8-15 er
__device__ int   g_cnt [PN];
__device__ int   g_off [PN + 1];
__device__ int   g_cur [PN];
__device__ int   g_srcs[PE];

#define ALD 36
#define BLD 132

__device__ __forceinline__ float4 cvt4(float4 v) {
    v.x = wmma::__float_to_tf32(v.x);
    v.y = wmma::__float_to_tf32(v.y);
    v.z = wmma::__float_to_tf32(v.z);
    v.w = wmma::__float_to_tf32(v.w);
    return v;
}

// ====== GEMM1: 128x128 tf32 tile, single-buffer, cvt-at-store (R9-proven) ======
union SmemU {
    struct { float As[128 * ALD]; float Bs[32 * BLD]; } ld;   // 35.3 KB
    float stage[64 * BLD];                                     // 33.8 KB
};

__global__ __launch_bounds__(256, 2)
void k_gemm1(const float* __restrict__ A, const float* __restrict__ W) {
    const int p    = blockIdx.z;
    const int row0 = blockIdx.y * 128;
    const int col0 = blockIdx.x * 128;
    const float* B = W + (size_t)p * IN_DIM * HD;
    float* C = g_feat + (size_t)p * N_NODES * HD;

    __shared__ SmemU sm;
    const int tid = threadIdx.x;
    const int warpId = tid >> 5;
    const int wm = warpId & 3;
    const int wn = warpId >> 2;

    wmma::fragment<wmma::accumulator, 16, 16, 8, float> acc[2][4];
    #pragma unroll
    for (int i = 0; i < 2; i++)
        #pragma unroll
        for (int j = 0; j < 4; j++)
            wmma::fill_fragment(acc[i][j], 0.f);

    #pragma unroll
    for (int s = 0; s < IN_DIM / 32; s++) {
        const int k0 = s << 5;
        #pragma unroll
        for (int t = 0; t < 4; t++) {
            int fid = tid + t * 256;
            int r = fid >> 3, kq = (fid & 7) << 2;
            int gr = row0 + r;
            float4 v = (gr < N_NODES)
                ? *(const float4*)&A[(size_t)gr * IN_DIM + k0 + kq]
                : make_float4(0.f, 0.f, 0.f, 0.f);
            *(float4*)&sm.ld.As[r * ALD + kq] = cvt4(v);
        }
        #pragma unroll
        for (int t = 0; t < 4; t++) {
            int fid = tid + t * 256;
            int kr = fid >> 5, c4 = (fid & 31) << 2;
            float4 v = *(const float4*)&B[(size_t)(k0 + kr) * HD + col0 + c4];
            *(float4*)&sm.ld.Bs[kr * BLD + c4] = cvt4(v);
        }
        __syncthreads();

        #pragma unroll
        for (int kk = 0; kk < 32; kk += 8) {
            wmma::fragment<wmma::matrix_a, 16, 16, 8, wmma::precision::tf32, wmma::row_major> af[2];
            wmma::fragment<wmma::matrix_b, 16, 16, 8, wmma::precision::tf32, wmma::row_major> bf[4];
            #pragma unroll
            for (int i = 0; i < 2; i++)
                wmma::load_matrix_sync(af[i], &sm.ld.As[(wm * 32 + i * 16) * ALD + kk], ALD);
            #pragma unroll
            for (int j = 0; j < 4; j++)
                wmma::load_matrix_sync(bf[j], &sm.ld.Bs[kk * BLD + wn * 64 + j * 16], BLD);
            #pragma unroll
            for (int i = 0; i < 2; i++)
                #pragma unroll
                for (int j = 0; j < 4; j++)
                    wmma::mma_sync(acc[i][j], af[i], bf[j], acc[i][j]);
        }
        __syncthreads();
    }

    #pragma unroll
    for (int half = 0; half < 2; half++) {
        if ((wm >> 1) == half) {
            #pragma unroll
            for (int i = 0; i < 2; i++)
                #pragma unroll
                for (int j = 0; j < 4; j++)
                    wmma::store_matrix_sync(
                        &sm.stage[((wm & 1) * 32 + i * 16) * BLD + wn * 64 + j * 16],
                        acc[i][j], BLD, wmma::mem_row_major);
        }
        __syncthreads();
        #pragma unroll
        for (int t = 0; t < 8; t++) {
            int fid = tid + t * 256;
            int r = fid >> 5, c4 = (fid & 31) << 2;
            int gr = row0 + half * 64 + r;
            if (gr < N_NODES)
                *(float4*)&C[(size_t)gr * HD + col0 + c4] =
                    *(const float4*)&sm.stage[r * BLD + c4];
        }
        __syncthreads();
    }
}

// ====== GEMM2: 64x128 tf32 tiles ======
union SmemU2 {
    struct { float As[64 * ALD]; float Bs[32 * BLD]; } ld;    // 26.1 KB
    float stage[64 * BLD];                                     // 33.8 KB
};

__global__ __launch_bounds__(256, 3)
void k_gemm2(const float* __restrict__ B, const float* __restrict__ bias,
             float* __restrict__ C) {
    __shared__ SmemU2 sm;
    const int tid = threadIdx.x;
    const int warpId = tid >> 5;
    const int wm = warpId & 1;
    const int wn = warpId >> 1;
    const int row0 = blockIdx.x * 64;

    wmma::fragment<wmma::accumulator, 16, 16, 8, float> acc[2][2];
    #pragma unroll
    for (int i = 0; i < 2; i++)
        #pragma unroll
        for (int j = 0; j < 2; j++)
            wmma::fill_fragment(acc[i][j], 0.f);

    for (int s = 0; s < PHD / 32; s++) {
        const int k0 = s << 5;
        #pragma unroll
        for (int t = 0; t < 2; t++) {
            int fid = tid + t * 256;
            int r = fid >> 3, kq = (fid & 7) << 2;
            int gr = row0 + r;
            float4 v = (gr < N_NODES)
                ? *(const float4*)&g_z[(size_t)gr * PHD + k0 + kq]
                : make_float4(0.f, 0.f, 0.f, 0.f);
            *(float4*)&sm.ld.As[r * ALD + kq] = cvt4(v);
        }
        #pragma unroll
        for (int t = 0; t < 4; t++) {
            int fid = tid + t * 256;
            int kr = fid >> 5, c4 = (fid & 31) << 2;
            float4 v = *(const float4*)&B[(size_t)(k0 + kr) * EMB + c4];
            *(float4*)&sm.ld.Bs[kr * BLD + c4] = cvt4(v);
        }
        __syncthreads();

        #pragma unroll
        for (int kk = 0; kk < 32; kk += 8) {
            wmma::fragment<wmma::matrix_a, 16, 16, 8, wmma::precision::tf32, wmma::row_major> af[2];
            wmma::fragment<wmma::matrix_b, 16, 16, 8, wmma::precision::tf32, wmma::row_major> bf[2];
            #pragma unroll
            for (int i = 0; i < 2; i++)
                wmma::load_matrix_sync(af[i], &sm.ld.As[(wm * 32 + i * 16) * ALD + kk], ALD);
            #pragma unroll
            for (int j = 0; j < 2; j++)
                wmma::load_matrix_sync(bf[j], &sm.ld.Bs[kk * BLD + wn * 32 + j * 16], BLD);
            #pragma unroll
            for (int i = 0; i < 2; i++)
                #pragma unroll
                for (int j = 0; j < 2; j++)
                    wmma::mma_sync(acc[i][j], af[i], bf[j], acc[i][j]);
        }
        __syncthreads();
    }

    #pragma unroll
    for (int i = 0; i < 2; i++)
        #pragma unroll
        for (int j = 0; j < 2; j++)
            wmma::store_matrix_sync(
                &sm.stage[(wm * 32 + i * 16) * BLD + wn * 32 + j * 16],
                acc[i][j], BLD, wmma::mem_row_major);
    __syncthreads();

    #pragma unroll
    for (int t = 0; t < 8; t++) {
        int fid = tid + t * 256;
        int r = fid >> 5, c4 = (fid & 31) << 2;
        int gr = row0 + r;
        if (gr < N_NODES) {
            float4 v = *(const float4*)&sm.stage[r * BLD + c4];
            v.x += bias[c4 + 0];
            v.y += bias[c4 + 1];
            v.z += bias[c4 + 2];
            v.w += bias[c4 + 3];
            *(float4*)&C[(size_t)gr * EMB + c4] = v;
        }
    }
}

// ====== wa precompute: wa[p][k][j] = sum_d W[p][k][h*32+d] * {al,ar}[p][h][d] ======
__global__ void k_wa(const float* __restrict__ W,
                     const float* __restrict__ al, const float* __restrict__ ar) {
    int idx = blockIdx.x * blockDim.x + threadIdx.x;
    if (idx >= P_PATHS * IN_DIM * 16) return;
    int p = idx >> 11;
    int k = (idx >> 4) & 127;
    int j = idx & 15;
    int h = j & 7;
    const float* v = ((j < 8) ? al : ar) + p * HD + h * D_DIM;
    const float* wrow = W + ((size_t)p * IN_DIM + k) * HD + h * D_DIM;
    float s = 0.f;
    #pragma unroll
    for (int d = 0; d < D_DIM; d++) s += wrow[d] * v[d];
    g_wa[idx] = s;
}

// ====== el/er = h @ wa : 64-node tiles, fp32, reads h (not feat) ======
__global__ __launch_bounds__(256)
void k_elr2(const float* __restrict__ A) {
    const int p = blockIdx.y;
    const int row0 = blockIdx.x * 64;

    __shared__ float sh[64 * 132];        // 33.8 KB
    __shared__ float swa[IN_DIM * 16];    // 8 KB

    const int tid = threadIdx.x;

    #pragma unroll
    for (int t = 0; t < 8; t++) {
        int fid = tid + t * 256;          // 2048 float4 = 64x128
        int r = fid >> 5, c4 = (fid & 31) << 2;
        int gr = row0 + r;
        float4 v = (gr < N_NODES)
            ? *(const float4*)&A[(size_t)gr * IN_DIM + c4]
            : make_float4(0.f, 0.f, 0.f, 0.f);
        *(float4*)&sh[r * 132 + c4] = v;
    }
    #pragma unroll
    for (int t = 0; t < 2; t++) {
        int fid = tid + t * 256;
        *(float4*)&swa[fid * 4] = *(const float4*)&g_wa[p * 2048 + fid * 4];
    }
    __syncthreads();

    const int nl = tid >> 2;
    const int j0 = (tid & 3) << 2;
    float acc0 = 0.f, acc1 = 0.f, acc2 = 0.f, acc3 = 0.f;
    const float* hrow = &sh[nl * 132];
    #pragma unroll 8
    for (int k = 0; k < IN_DIM; k++) {
        float hv = hrow[k];
        const float* wk = &swa[k * 16 + j0];
        acc0 += hv * wk[0];
        acc1 += hv * wk[1];
        acc2 += hv * wk[2];
        acc3 += hv * wk[3];
    }

    int gr = row0 + nl;
    if (gr < N_NODES) {
        float* outp = (j0 < 8) ? &g_el[(p * N_NODES + gr) * H_HEADS + j0]
                               : &g_er[(p * N_NODES + gr) * H_HEADS + (j0 - 8)];
        outp[0] = acc0; outp[1] = acc1; outp[2] = acc2; outp[3] = acc3;
    }
}

// ================= CSR build =================
__global__ void k_zero_cnt() {
    int i = blockIdx.x * blockDim.x + threadIdx.x;
    if (i < PN / 4) ((int4*)g_cnt)[i] = make_int4(0, 0, 0, 0);
}

__global__ void k_csr_count(const int* __restrict__ ei) {
    int idx = blockIdx.x * blockDim.x + threadIdx.x;
    if (idx >= PE) return;
    int p = idx / E_EDGES, e = idx % E_EDGES;
    int dst = ei[(size_t)p * 2 * E_EDGES + E_EDGES + e];
    atomicAdd(&g_cnt[p * N_NODES + dst], 1);
}

__global__ void k_scan() {
    __shared__ int warp_sums[32];
    __shared__ int s_carry;
    const int tid = threadIdx.x, lane = tid & 31, w = tid >> 5;
    if (tid == 0) s_carry = 0;
    __syncthreads();

    for (int base = 0; base < PN; base += 4096) {
        int i0 = base + tid * 4;
        int v[4];
        #pragma unroll
        for (int j = 0; j < 4; j++) v[j] = (i0 + j < PN) ? g_cnt[i0 + j] : 0;
        int tsum = v[0] + v[1] + v[2] + v[3];

        int x = tsum;
        #pragma unroll
        for (int o = 1; o < 32; o <<= 1) {
            int t = __shfl_up_sync(0xFFFFFFFFu, x, o);
            if (lane >= o) x += t;
        }
        if (lane == 31) warp_sums[w] = x;
        __syncthreads();
        if (w == 0) {
            int y = warp_sums[lane];
            #pragma unroll
            for (int o = 1; o < 32; o <<= 1) {
                int t = __shfl_up_sync(0xFFFFFFFFu, y, o);
                if (lane >= o) y += t;
            }
            warp_sums[lane] = y;
        }
        __syncthreads();

        int excl = s_carry + (w ? warp_sums[w - 1] : 0) + x - tsum;
        int run = excl;
        #pragma unroll
        for (int j = 0; j < 4; j++) {
            if (i0 + j < PN) { g_off[i0 + j] = run; g_cur[i0 + j] = run; }
            run += v[j];
        }
        __syncthreads();
        if (tid == 0) s_carry += warp_sums[31];
        __syncthreads();
    }
    if (tid == 0) g_off[PN] = s_carry;
}

__global__ void k_csr_scatter(const int* __restrict__ ei) {
    int idx = blockIdx.x * blockDim.x + threadIdx.x;
    if (idx >= PE) return;
    int p = idx / E_EDGES, e = idx % E_EDGES;
    const int* eip = ei + (size_t)p * 2 * E_EDGES;
    int src = eip[e];
    int dst = eip[E_EDGES + e];
    int pos = atomicAdd(&g_cur[p * N_NODES + dst], 1);
    g_srcs[pos] = src;
}

// ================= fused attention: warp per (dst, p) =================
__global__ __launch_bounds__(256)
void k_agg() {
    const int p    = blockIdx.y;
    const int w    = threadIdx.x >> 5;
    const int lane = threadIdx.x & 31;
    const int dst  = blockIdx.x * 8 + w;
    const int b    = p * N_NODES + dst;

    const int o0  = g_off[b];
    const int deg = g_off[b + 1] - o0;

    __shared__ int   s_src[8][A_CAP];
    __shared__ float s_a  [8][A_CAP * H_HEADS];

    const int nc = (deg < A_CAP) ? deg : A_CAP;
    for (int i = lane; i < nc; i += 32) s_src[w][i] = g_srcs[o0 + i];
    __syncwarp();

    const int   hA   = lane & 7;
    const float er_h = g_er[b * H_HEADS + hA];

    float m = -1e30f, s = 0.f;
    for (int base = 0; base < nc; base += 4) {
        int i = base + (lane >> 3);
        if (i < nc) {
            int src = s_src[w][i];
            float v = g_el[(p * N_NODES + src) * H_HEADS + hA] + er_h;
            v = (v > 0.f) ? v : 0.2f * v;
            s_a[w][i * 8 + hA] = v;
            if (v > m) { s = s * __expf(m - v) + 1.f; m = v; }
            else       { s += __expf(v - m); }
        }
    }
    for (int base = A_CAP; base < deg; base += 4) {
        int i = base + (lane >> 3);
        if (i < deg) {
            int src = g_srcs[o0 + i];
            float v = g_el[(p * N_NODES + src) * H_HEADS + hA] + er_h;
            v = (v > 0.f) ? v : 0.2f * v;
            if (v > m) { s = s * __expf(m - v) + 1.f; m = v; }
            else       { s += __expf(v - m); }
        }
    }
    #pragma unroll
    for (int o = 8; o < 32; o <<= 1) {
        float mo = __shfl_xor_sync(0xFFFFFFFFu, m, o);
        float so = __shfl_xor_sync(0xFFFFFFFFu, s, o);
        float mn = fmaxf(m, mo);
        s = s * __expf(m - mn) + so * __expf(mo - mn);
        m = mn;
    }
    const float invd = (s > 0.f) ? 1.f / s : 0.f;

    for (int base = 0; base < nc; base += 4) {
        int i = base + (lane >> 3);
        if (i < nc) {
            float v = s_a[w][i * 8 + hA];
            s_a[w][i * 8 + hA] = __expf(v - m) * invd;
        }
    }
    __syncwarp();

    const int hB = lane >> 2;
    const float mB  = __shfl_sync(0xFFFFFFFFu, m,    hB);
    const float iB  = __shfl_sync(0xFFFFFFFFu, invd, hB);
    const float erB = __shfl_sync(0xFFFFFFFFu, er_h, hB);

    float4 a0 = make_float4(0.f, 0.f, 0.f, 0.f);
    float4 a1 = make_float4(0.f, 0.f, 0.f, 0.f);
    const float* fbase = g_feat + (size_t)p * N_NODES * HD;

    int i = 0;
    for (; i + 2 <= nc; i += 2) {
        int   s0 = s_src[w][i];
        int   s1 = s_src[w][i + 1];
        float w0 = s_a[w][i * 8 + hB];
        float w1 = s_a[w][(i + 1) * 8 + hB];
        const float4* fr0 = (const float4*)(fbase + (size_t)s0 * HD + lane * 8);
        const float4* fr1 = (const float4*)(fbase + (size_t)s1 * HD + lane * 8);
        float4 x0 = fr0[0], x1 = fr0[1];
        float4 y0 = fr1[0], y1 = fr1[1];
        a0.x += w0 * x0.x; a0.y += w0 * x0.y; a0.z += w0 * x0.z; a0.w += w0 * x0.w;
        a1.x += w0 * x1.x; a1.y += w0 * x1.y; a1.z += w0 * x1.z; a1.w += w0 * x1.w;
        a0.x += w1 * y0.x; a0.y += w1 * y0.y; a0.z += w1 * y0.z; a0.w += w1 * y0.w;
        a1.x += w1 * y1.x; a1.y += w1 * y1.y; a1.z += w1 * y1.z; a1.w += w1 * y1.w;
    }
    for (; i < nc; i++) {
        int   src = s_src[w][i];
        float a   = s_a[w][i * 8 + hB];
        const float4* fr = (const float4*)(fbase + (size_t)src * HD + lane * 8);
        float4 f0 = fr[0], f1 = fr[1];
        a0.x += a * f0.x; a0.y += a * f0.y; a0.z += a * f0.z; a0.w += a * f0.w;
        a1.x += a * f1.x; a1.y += a * f1.y; a1.z += a * f1.z; a1.w += a * f1.w;
    }
    for (i = nc; i < deg; i++) {
        int src = g_srcs[o0 + i];
        float v = g_el[(p * N_NODES + src) * H_HEADS + hB] + erB;
        v = (v > 0.f) ? v : 0.2f * v;
        float a = __expf(v - mB) * iB;
        const float4* fr = (const float4*)(fbase + (size_t)src * HD + lane * 8);
        float4 f0 = fr[0], f1 = fr[1];
        a0.x += a * f0.x; a0.y += a * f0.y; a0.z += a * f0.z; a0.w += a * f0.w;
        a1.x += a * f1.x; a1.y += a * f1.y; a1.z += a * f1.z; a1.w += a * f1.w;
    }

    a0.x = (a0.x > 0.f) ? a0.x : expm1f(a0.x);
    a0.y = (a0.y > 0.f) ? a0.y : expm1f(a0.y);
    a0.z = (a0.z > 0.f) ? a0.z : expm1f(a0.z);
    a0.w = (a0.w > 0.f) ? a0.w : expm1f(a0.w);
    a1.x = (a1.x > 0.f) ? a1.x : expm1f(a1.x);
    a1.y = (a1.y > 0.f) ? a1.y : expm1f(a1.y);
    a1.z = (a1.z > 0.f) ? a1.z : expm1f(a1.z);
    a1.w = (a1.w > 0.f) ? a1.w : expm1f(a1.w);

    float* zp = g_z + (size_t)dst * PHD + p * HD + lane * 8;
    *(float4*)zp       = a0;
    *(float4*)(zp + 4) = a1;
}

extern "C" void kernel_launch(void* const* d_in, const int* in_sizes, int n_in,
                              void* d_out, int out_size) {
    const float* h     = (const float*)d_in[0];
    const int*   ei    = (const int*)  d_in[1];
    const float* fc_w  = (const float*)d_in[2];
    const float* al    = (const float*)d_in[3];
    const float* ar    = (const float*)d_in[4];
    const float* sem_w = (const float*)d_in[5];
    const float* sem_b = (const float*)d_in[6];
    float* out = (float*)d_out;

    // order keeps k_gemm1 in the profiler's captured slot (4th launch)
    k_zero_cnt   <<<(PN / 4 + 255) / 256, 256>>>();
    k_csr_count  <<<(PE + 255) / 256, 256>>>(ei);
    k_wa         <<<(P_PATHS * IN_DIM * 16 + 255) / 256, 256>>>(fc_w, al, ar);
    k_gemm1<<<dim3(HD / 128, (N_NODES + 127) / 128, P_PATHS), 256>>>(h, fc_w);
    k_elr2 <<<dim3((N_NODES + 63) / 64, P_PATHS), 256>>>(h);
    k_scan       <<<1, 1024>>>();
    k_csr_scatter<<<(PE + 255) / 256, 256>>>(ei);

    k_agg<<<dim3(N_NODES / 8, P_PATHS), 256>>>();

    k_gemm2<<<(N_NODES + 63) / 64, 256>>>(sem_w, sem_b, out);
}

// round 14
// speedup vs baseline: 1.0573x; 1.0573x over previous
#include <cuda_runtime.h>
#include <mma.h>
#include <math.h>

using namespace nvcuda;

#define N_NODES 50000
#define E_EDGES 800000
#define P_PATHS 3
#define IN_DIM  128
#define H_HEADS 8
#define D_DIM   32
#define HD      256   // H*D
#define PHD     768   // P*H*D
#define EMB     128
#define PN      (P_PATHS * N_NODES)        // 150000
#define PE      (P_PATHS * E_EDGES)        // 2400000
#define A_CAP   64

// ---- scratch (static device memory) ----
__device__ float g_feat[(size_t)P_PATHS * N_NODES * HD];   // 153.6 MB
__device__ float g_el  [PN * H_HEADS];
__device__ float g_er  [PN * H_HEADS];
__device__ float g_z   [(size_t)N_NODES * PHD];            // 153.6 MB (post-ELU)
__device__ float g_wa  [P_PATHS * IN_DIM * 16];            // [p][k][16]: 0-7 el, 8-15 er
__device__ int   g_cnt [PN];
__device__ int   g_off [PN + 1];
__device__ int   g_cur [PN];
__device__ int   g_srcs[PE];

#define ALD 36
#define BLD 132

__device__ __forceinline__ float4 cvt4(float4 v) {
    v.x = wmma::__float_to_tf32(v.x);
    v.y = wmma::__float_to_tf32(v.y);
    v.z = wmma::__float_to_tf32(v.z);
    v.w = wmma::__float_to_tf32(v.w);
    return v;
}

// ====== unified 64x128 tf32 WMMA GEMM (3 CTA/SM recipe, proven on gemm2) ======
union SmemU64 {
    struct { float As[64 * ALD]; float Bs[32 * BLD]; } ld;    // 26.1 KB
    float stage[64 * BLD];                                     // 33.8 KB
};

__device__ __forceinline__ void wmma_gemm64(
    const float* __restrict__ A, int lda,
    const float* __restrict__ B, int ldb,
    float* __restrict__ C, int ldc,
    int Ktot, const float* __restrict__ bias,
    int row0, int col0)
{
    __shared__ SmemU64 sm;
    const int tid = threadIdx.x;
    const int warpId = tid >> 5;
    const int wm = warpId & 1;       // 32-row stripe
    const int wn = warpId >> 1;      // 32-col stripe

    wmma::fragment<wmma::accumulator, 16, 16, 8, float> acc[2][2];
    #pragma unroll
    for (int i = 0; i < 2; i++)
        #pragma unroll
        for (int j = 0; j < 2; j++)
            wmma::fill_fragment(acc[i][j], 0.f);

    for (int s = 0; s < Ktot / 32; s++) {
        const int k0 = s << 5;
        #pragma unroll
        for (int t = 0; t < 2; t++) {              // A: 64x32 = 512 float4
            int fid = tid + t * 256;
            int r = fid >> 3, kq = (fid & 7) << 2;
            int gr = row0 + r;
            float4 v = (gr < N_NODES)
                ? *(const float4*)&A[(size_t)gr * lda + k0 + kq]
                : make_float4(0.f, 0.f, 0.f, 0.f);
            *(float4*)&sm.ld.As[r * ALD + kq] = cvt4(v);
        }
        #pragma unroll
        for (int t = 0; t < 4; t++) {              // B: 32x128 = 1024 float4
            int fid = tid + t * 256;
            int kr = fid >> 5, c4 = (fid & 31) << 2;
            float4 v = *(const float4*)&B[(size_t)(k0 + kr) * ldb + col0 + c4];
            *(float4*)&sm.ld.Bs[kr * BLD + c4] = cvt4(v);
        }
        __syncthreads();

        #pragma unroll
        for (int kk = 0; kk < 32; kk += 8) {
            wmma::fragment<wmma::matrix_a, 16, 16, 8, wmma::precision::tf32, wmma::row_major> af[2];
            wmma::fragment<wmma::matrix_b, 16, 16, 8, wmma::precision::tf32, wmma::row_major> bf[2];
            #pragma unroll
            for (int i = 0; i < 2; i++)
                wmma::load_matrix_sync(af[i], &sm.ld.As[(wm * 32 + i * 16) * ALD + kk], ALD);
            #pragma unroll
            for (int j = 0; j < 2; j++)
                wmma::load_matrix_sync(bf[j], &sm.ld.Bs[kk * BLD + wn * 32 + j * 16], BLD);
            #pragma unroll
            for (int i = 0; i < 2; i++)
                #pragma unroll
                for (int j = 0; j < 2; j++)
                    wmma::mma_sync(acc[i][j], af[i], bf[j], acc[i][j]);
        }
        __syncthreads();
    }

    #pragma unroll
    for (int i = 0; i < 2; i++)
        #pragma unroll
        for (int j = 0; j < 2; j++)
            wmma::store_matrix_sync(
                &sm.stage[(wm * 32 + i * 16) * BLD + wn * 32 + j * 16],
                acc[i][j], BLD, wmma::mem_row_major);
    __syncthreads();

    #pragma unroll
    for (int t = 0; t < 8; t++) {
        int fid = tid + t * 256;                   // 64x32 float4
        int r = fid >> 5, c4 = (fid & 31) << 2;
        int gr = row0 + r;
        if (gr < N_NODES) {
            float4 v = *(const float4*)&sm.stage[r * BLD + c4];
            if (bias) {
                v.x += bias[col0 + c4 + 0];
                v.y += bias[col0 + c4 + 1];
                v.z += bias[col0 + c4 + 2];
                v.w += bias[col0 + c4 + 3];
            }
            *(float4*)&C[(size_t)gr * ldc + col0 + c4] = v;
        }
    }
}

__global__ __launch_bounds__(256, 3)
void k_gemm1(const float* __restrict__ A, const float* __restrict__ W) {
    const int p = blockIdx.z;
    wmma_gemm64(A, IN_DIM,
                W + (size_t)p * IN_DIM * HD, HD,
                g_feat + (size_t)p * N_NODES * HD, HD,
                IN_DIM, 0,
                blockIdx.y * 64, blockIdx.x * 128);
}

__global__ __launch_bounds__(256, 3)
void k_gemm2(const float* __restrict__ B, const float* __restrict__ bias,
             float* __restrict__ C) {
    wmma_gemm64(g_z, PHD,
                B, EMB,
                C, EMB,
                PHD, bias,
                blockIdx.y * 64, 0);
}

// ====== wa precompute: wa[p][k][j] = sum_d W[p][k][h*32+d] * {al,ar}[p][h][d] ======
__global__ void k_wa(const float* __restrict__ W,
                     const float* __restrict__ al, const float* __restrict__ ar) {
    int idx = blockIdx.x * blockDim.x + threadIdx.x;
    if (idx >= P_PATHS * IN_DIM * 16) return;
    int p = idx >> 11;
    int k = (idx >> 4) & 127;
    int j = idx & 15;
    int h = j & 7;
    const float* v = ((j < 8) ? al : ar) + p * HD + h * D_DIM;
    const float* wrow = W + ((size_t)p * IN_DIM + k) * HD + h * D_DIM;
    float s = 0.f;
    #pragma unroll
    for (int d = 0; d < D_DIM; d++) s += wrow[d] * v[d];
    g_wa[idx] = s;
}

// ====== el/er = h @ wa : 64-node tiles, fp32, reads h (not feat) ======
__global__ __launch_bounds__(256)
void k_elr2(const float* __restrict__ A) {
    const int p = blockIdx.y;
    const int row0 = blockIdx.x * 64;

    __shared__ float sh[64 * 132];        // 33.8 KB
    __shared__ float swa[IN_DIM * 16];    // 8 KB

    const int tid = threadIdx.x;

    #pragma unroll
    for (int t = 0; t < 8; t++) {
        int fid = tid + t * 256;          // 2048 float4 = 64x128
        int r = fid >> 5, c4 = (fid & 31) << 2;
        int gr = row0 + r;
        float4 v = (gr < N_NODES)
            ? *(const float4*)&A[(size_t)gr * IN_DIM + c4]
            : make_float4(0.f, 0.f, 0.f, 0.f);
        *(float4*)&sh[r * 132 + c4] = v;
    }
    #pragma unroll
    for (int t = 0; t < 2; t++) {
        int fid = tid + t * 256;
        *(float4*)&swa[fid * 4] = *(const float4*)&g_wa[p * 2048 + fid * 4];
    }
    __syncthreads();

    const int nl = tid >> 2;
    const int j0 = (tid & 3) << 2;
    float acc0 = 0.f, acc1 = 0.f, acc2 = 0.f, acc3 = 0.f;
    const float* hrow = &sh[nl * 132];
    #pragma unroll 8
    for (int k = 0; k < IN_DIM; k++) {
        float hv = hrow[k];
        const float* wk = &swa[k * 16 + j0];
        acc0 += hv * wk[0];
        acc1 += hv * wk[1];
        acc2 += hv * wk[2];
        acc3 += hv * wk[3];
    }

    int gr = row0 + nl;
    if (gr < N_NODES) {
        float* outp = (j0 < 8) ? &g_el[(p * N_NODES + gr) * H_HEADS + j0]
                               : &g_er[(p * N_NODES + gr) * H_HEADS + (j0 - 8)];
        outp[0] = acc0; outp[1] = acc1; outp[2] = acc2; outp[3] = acc3;
    }
}

// ================= CSR build =================
__global__ void k_zero_cnt() {
    int i = blockIdx.x * blockDim.x + threadIdx.x;
    if (i < PN / 4) ((int4*)g_cnt)[i] = make_int4(0, 0, 0, 0);
}

__global__ void k_csr_count(const int* __restrict__ ei) {
    int idx = blockIdx.x * blockDim.x + threadIdx.x;
    if (idx >= PE) return;
    int p = idx / E_EDGES, e = idx % E_EDGES;
    int dst = ei[(size_t)p * 2 * E_EDGES + E_EDGES + e];
    atomicAdd(&g_cnt[p * N_NODES + dst], 1);
}

__global__ void k_scan() {
    __shared__ int warp_sums[32];
    __shared__ int s_carry;
    const int tid = threadIdx.x, lane = tid & 31, w = tid >> 5;
    if (tid == 0) s_carry = 0;
    __syncthreads();

    for (int base = 0; base < PN; base += 4096) {
        int i0 = base + tid * 4;
        int v[4];
        #pragma unroll
        for (int j = 0; j < 4; j++) v[j] = (i0 + j < PN) ? g_cnt[i0 + j] : 0;
        int tsum = v[0] + v[1] + v[2] + v[3];

        int x = tsum;
        #pragma unroll
        for (int o = 1; o < 32; o <<= 1) {
            int t = __shfl_up_sync(0xFFFFFFFFu, x, o);
            if (lane >= o) x += t;
        }
        if (lane == 31) warp_sums[w] = x;
        __syncthreads();
        if (w == 0) {
            int y = warp_sums[lane];
            #pragma unroll
            for (int o = 1; o < 32; o <<= 1) {
                int t = __shfl_up_sync(0xFFFFFFFFu, y, o);
                if (lane >= o) y += t;
            }
            warp_sums[lane] = y;
        }
        __syncthreads();

        int excl = s_carry + (w ? warp_sums[w - 1] : 0) + x - tsum;
        int run = excl;
        #pragma unroll
        for (int j = 0; j < 4; j++) {
            if (i0 + j < PN) { g_off[i0 + j] = run; g_cur[i0 + j] = run; }
            run += v[j];
        }
        __syncthreads();
        if (tid == 0) s_carry += warp_sums[31];
        __syncthreads();
    }
    if (tid == 0) g_off[PN] = s_carry;
}

__global__ void k_csr_scatter(const int* __restrict__ ei) {
    int idx = blockIdx.x * blockDim.x + threadIdx.x;
    if (idx >= PE) return;
    int p = idx / E_EDGES, e = idx % E_EDGES;
    const int* eip = ei + (size_t)p * 2 * E_EDGES;
    int src = eip[e];
    int dst = eip[E_EDGES + e];
    int pos = atomicAdd(&g_cur[p * N_NODES + dst], 1);
    g_srcs[pos] = src;
}

// ================= fused attention: warp per (dst, p) =================
__global__ __launch_bounds__(256)
void k_agg() {
    const int p    = blockIdx.y;
    const int w    = threadIdx.x >> 5;
    const int lane = threadIdx.x & 31;
    const int dst  = blockIdx.x * 8 + w;
    const int b    = p * N_NODES + dst;

    const int o0  = g_off[b];
    const int deg = g_off[b + 1] - o0;

    __shared__ int   s_src[8][A_CAP];
    __shared__ float s_a  [8][A_CAP * H_HEADS];

    const int nc = (deg < A_CAP) ? deg : A_CAP;
    for (int i = lane; i < nc; i += 32) s_src[w][i] = g_srcs[o0 + i];
    __syncwarp();

    const int   hA   = lane & 7;
    const float er_h = g_er[b * H_HEADS + hA];

    float m = -1e30f, s = 0.f;
    for (int base = 0; base < nc; base += 4) {
        int i = base + (lane >> 3);
        if (i < nc) {
            int src = s_src[w][i];
            float v = g_el[(p * N_NODES + src) * H_HEADS + hA] + er_h;
            v = (v > 0.f) ? v : 0.2f * v;
            s_a[w][i * 8 + hA] = v;
            if (v > m) { s = s * __expf(m - v) + 1.f; m = v; }
            else       { s += __expf(v - m); }
        }
    }
    for (int base = A_CAP; base < deg; base += 4) {
        int i = base + (lane >> 3);
        if (i < deg) {
            int src = g_srcs[o0 + i];
            float v = g_el[(p * N_NODES + src) * H_HEADS + hA] + er_h;
            v = (v > 0.f) ? v : 0.2f * v;
            if (v > m) { s = s * __expf(m - v) + 1.f; m = v; }
            else       { s += __expf(v - m); }
        }
    }
    #pragma unroll
    for (int o = 8; o < 32; o <<= 1) {
        float mo = __shfl_xor_sync(0xFFFFFFFFu, m, o);
        float so = __shfl_xor_sync(0xFFFFFFFFu, s, o);
        float mn = fmaxf(m, mo);
        s = s * __expf(m - mn) + so * __expf(mo - mn);
        m = mn;
    }
    const float invd = (s > 0.f) ? 1.f / s : 0.f;

    for (int base = 0; base < nc; base += 4) {
        int i = base + (lane >> 3);
        if (i < nc) {
            float v = s_a[w][i * 8 + hA];
            s_a[w][i * 8 + hA] = __expf(v - m) * invd;
        }
    }
    __syncwarp();

    const int hB = lane >> 2;
    const float mB  = __shfl_sync(0xFFFFFFFFu, m,    hB);
    const float iB  = __shfl_sync(0xFFFFFFFFu, invd, hB);
    const float erB = __shfl_sync(0xFFFFFFFFu, er_h, hB);

    float4 a0 = make_float4(0.f, 0.f, 0.f, 0.f);
    float4 a1 = make_float4(0.f, 0.f, 0.f, 0.f);
    const float* fbase = g_feat + (size_t)p * N_NODES * HD;

    int i = 0;
    for (; i + 2 <= nc; i += 2) {
        int   s0 = s_src[w][i];
        int   s1 = s_src[w][i + 1];
        float w0 = s_a[w][i * 8 + hB];
        float w1 = s_a[w][(i + 1) * 8 + hB];
        const float4* fr0 = (const float4*)(fbase + (size_t)s0 * HD + lane * 8);
        const float4* fr1 = (const float4*)(fbase + (size_t)s1 * HD + lane * 8);
        float4 x0 = fr0[0], x1 = fr0[1];
        float4 y0 = fr1[0], y1 = fr1[1];
        a0.x += w0 * x0.x; a0.y += w0 * x0.y; a0.z += w0 * x0.z; a0.w += w0 * x0.w;
        a1.x += w0 * x1.x; a1.y += w0 * x1.y; a1.z += w0 * x1.z; a1.w += w0 * x1.w;
        a0.x += w1 * y0.x; a0.y += w1 * y0.y; a0.z += w1 * y0.z; a0.w += w1 * y0.w;
        a1.x += w1 * y1.x; a1.y += w1 * y1.y; a1.z += w1 * y1.z; a1.w += w1 * y1.w;
    }
    for (; i < nc; i++) {
        int   src = s_src[w][i];
        float a   = s_a[w][i * 8 + hB];
        const float4* fr = (const float4*)(fbase + (size_t)src * HD + lane * 8);
        float4 f0 = fr[0], f1 = fr[1];
        a0.x += a * f0.x; a0.y += a * f0.y; a0.z += a * f0.z; a0.w += a * f0.w;
        a1.x += a * f1.x; a1.y += a * f1.y; a1.z += a * f1.z; a1.w += a * f1.w;
    }
    for (i = nc; i < deg; i++) {
        int src = g_srcs[o0 + i];
        float v = g_el[(p * N_NODES + src) * H_HEADS + hB] + erB;
        v = (v > 0.f) ? v : 0.2f * v;
        float a = __expf(v - mB) * iB;
        const float4* fr = (const float4*)(fbase + (size_t)src * HD + lane * 8);
        float4 f0 = fr[0], f1 = fr[1];
        a0.x += a * f0.x; a0.y += a * f0.y; a0.z += a * f0.z; a0.w += a * f0.w;
        a1.x += a * f1.x; a1.y += a * f1.y; a1.z += a * f1.z; a1.w += a * f1.w;
    }

    a0.x = (a0.x > 0.f) ? a0.x : expm1f(a0.x);
    a0.y = (a0.y > 0.f) ? a0.y : expm1f(a0.y);
    a0.z = (a0.z > 0.f) ? a0.z : expm1f(a0.z);
    a0.w = (a0.w > 0.f) ? a0.w : expm1f(a0.w);
    a1.x = (a1.x > 0.f) ? a1.x : expm1f(a1.x);
    a1.y = (a1.y > 0.f) ? a1.y : expm1f(a1.y);
    a1.z = (a1.z > 0.f) ? a1.z : expm1f(a1.z);
    a1.w = (a1.w > 0.f) ? a1.w : expm1f(a1.w);

    float* zp = g_z + (size_t)dst * PHD + p * HD + lane * 8;
    *(float4*)zp       = a0;
    *(float4*)(zp + 4) = a1;
}

extern "C" void kernel_launch(void* const* d_in, const int* in_sizes, int n_in,
                              void* d_out, int out_size) {
    const float* h     = (const float*)d_in[0];
    const int*   ei    = (const int*)  d_in[1];
    const float* fc_w  = (const float*)d_in[2];
    const float* al    = (const float*)d_in[3];
    const float* ar    = (const float*)d_in[4];
    const float* sem_w = (const float*)d_in[5];
    const float* sem_b = (const float*)d_in[6];
    float* out = (float*)d_out;

    // order keeps k_gemm1 in the profiler's captured slot (4th launch)
    k_zero_cnt   <<<(PN / 4 + 255) / 256, 256>>>();
    k_csr_count  <<<(PE + 255) / 256, 256>>>(ei);
    k_wa         <<<(P_PATHS * IN_DIM * 16 + 255) / 256, 256>>>(fc_w, al, ar);
    k_gemm1<<<dim3(HD / 128, (N_NODES + 63) / 64, P_PATHS), 256>>>(h, fc_w);
    k_elr2 <<<dim3((N_NODES + 63) / 64, P_PATHS), 256>>>(h);
    k_scan       <<<1, 1024>>>();
    k_csr_scatter<<<(PE + 255) / 256, 256>>>(ei);

    k_agg<<<dim3(N_NODES / 8, P_PATHS), 256>>>();

    k_gemm2<<<dim3(1, (N_NODES + 63) / 64, 1), 256>>>(sem_w, sem_b, out);
}